// round 11
// baseline (speedup 1.0000x reference)
#include <cuda_runtime.h>
#include <math.h>

// ---------------- problem constants ----------------------------------------
#define E_TOTAL 600000
#define NDST    10000
#define DN      100
#define DE      172
#define DTF     100
#define DOUT    128
#define HEADS   2
#define KV_IN   372   // DN + DE + DTF
#define OUT_IN  228   // DOUT + DN
#define TE      32    // edges per block in the big GEMM
#define PITCH   36    // smem row pitch in floats (16B aligned, low-conflict)
#define SMEM_EDGE_BYTES (KV_IN * PITCH * 4)
#define QWROW   (KV_IN * HEADS)   // 744 floats per dst row in the QW table
#define QWN     8                 // nodes per block in k_qw

// ---------------- scratch (device globals) ---------------------------------
__device__ float g_qnodes[NDST * DOUT];
__device__ float g_qw[NDST * QWROW];     // QW[d][k][h] = sum_j q[d,h*64+j]*wk[k,h*64+j]
__device__ float g_z[NDST * HEADS];
__device__ float g_agg[NDST * DOUT];

// ---------------- packed f32x2 helpers --------------------------------------
__device__ __forceinline__ unsigned long long pack2(float a, float b) {
    unsigned long long r;
    asm("mov.b64 %0, {%1, %2};" : "=l"(r) : "f"(a), "f"(b));
    return r;
}
__device__ __forceinline__ void unpack2(unsigned long long v, float& a, float& b) {
    asm("mov.b64 {%0, %1}, %2;" : "=f"(a), "=f"(b) : "l"(v));
}
__device__ __forceinline__ void ffma2(unsigned long long& d,
                                      unsigned long long a, unsigned long long b) {
    asm("fma.rn.f32x2 %0, %1, %2, %0;" : "+l"(d) : "l"(a), "l"(b));
}

// ---------------- init: zero softmax Z + aggregation buffer ----------------
__global__ void k_init() {
    int i = blockIdx.x * blockDim.x + threadIdx.x;
    int stride = gridDim.x * blockDim.x;
    for (int k = i; k < NDST * HEADS; k += stride) g_z[k] = 0.f;
    for (int k = i; k < NDST * DOUT; k += stride)  g_agg[k] = 0.f;
}

// ---------------- Q per dst node -------------------------------------------
__global__ __launch_bounds__(128) void k_qnodes(
    const float* __restrict__ h, const float* __restrict__ wq,
    const float* __restrict__ bq, const float* __restrict__ time_b)
{
    int j  = threadIdx.x;
    int n0 = blockIdx.x * 4;
    __shared__ float sh[4][DN];
    for (int idx = j; idx < 4 * DN; idx += 128) {
        int n = idx / DN, i = idx % DN;
        sh[n][i] = h[(size_t)(n0 + n) * DN + i];
    }
    __syncthreads();
    float qc = bq[j];
    for (int i = 0; i < DTF; i++)
        qc = fmaf(wq[(DN + i) * DOUT + j], cosf(time_b[i]), qc);
    float a0 = qc, a1 = qc, a2 = qc, a3 = qc;
    for (int i = 0; i < DN; i++) {
        float w = wq[i * DOUT + j];
        a0 = fmaf(sh[0][i], w, a0);
        a1 = fmaf(sh[1][i], w, a1);
        a2 = fmaf(sh[2][i], w, a2);
        a3 = fmaf(sh[3][i], w, a3);
    }
    g_qnodes[(n0 + 0) * DOUT + j] = a0;
    g_qnodes[(n0 + 1) * DOUT + j] = a1;
    g_qnodes[(n0 + 2) * DOUT + j] = a2;
    g_qnodes[(n0 + 3) * DOUT + j] = a3;
}

// ---------------- QW table: fold Q into wk per dst node --------------------
// QW[d][k][h] = sum_{j<64} q[d][h*64+j] * wk[k][h*64+j]
__global__ __launch_bounds__(128) void k_qw(const float* __restrict__ wk) {
    int n0 = blockIdx.x * QWN;
    __shared__ float sq[QWN][DOUT];
    for (int idx = threadIdx.x; idx < QWN * DOUT; idx += 128) {
        int n = idx >> 7, j = idx & 127;
        sq[n][j] = g_qnodes[(size_t)(n0 + n) * DOUT + j];
    }
    __syncthreads();

    for (int k = threadIdx.x; k < KV_IN; k += 128) {
        const float* wr = wk + (size_t)k * DOUT;
        #pragma unroll
        for (int hh = 0; hh < HEADS; hh++) {
            float a[QWN];
            #pragma unroll
            for (int n = 0; n < QWN; n++) a[n] = 0.f;
            for (int j = 0; j < 64; j++) {
                float w = wr[hh * 64 + j];
                #pragma unroll
                for (int n = 0; n < QWN; n++)
                    a[n] = fmaf(sq[n][hh * 64 + j], w, a[n]);
            }
            #pragma unroll
            for (int n = 0; n < QWN; n++)
                g_qw[(size_t)(n0 + n) * QWROW + k * HEADS + hh] = a[n];
        }
    }
}

// ---------------- fused edge kernel: V GEMM + scores + aggregation ---------
// Register-tiled V GEMM: thread = 8 edges x 4 cols; warp = 32 edges x 32 cols.
// Per k: 2 LDS.128 (x edge-pairs, no packing) + 1 LDG.128 (4 wv cols) +
// 16 FFMA2 -> crossbar pressure 4x lower than R9, FFMA2 pipe is the limiter.
// Scores from the QW trick; exp w/o max-sub; z/agg via L2 atomics.
__global__ __launch_bounds__(128, 4) void k_edge(
    const float* __restrict__ h,  const float* __restrict__ ef,
    const float* __restrict__ dt, const int*   __restrict__ dst_idx,
    const float* __restrict__ time_w, const float* __restrict__ time_b,
    const float* __restrict__ wv, const float* __restrict__ bv,
    const float* __restrict__ att_bias)
{
    extern __shared__ float s_in[];      // [KV_IN][PITCH], uses first TE cols
    __shared__ int   s_dst[TE];
    __shared__ float s_dt[TE];
    __shared__ float s_ab[2];
    __shared__ float s_w[TE][HEADS];

    int j  = threadIdx.x;
    int e0 = blockIdx.x * TE;

    if (j < TE) { s_dst[j] = dst_idx[e0 + j]; s_dt[j] = dt[e0 + j]; }
    if (j < 2) {
        float s = 0.f;
        #pragma unroll 8
        for (int i = 0; i < 64; i++) s += att_bias[j * 64 + i];
        s_ab[j] = s;
    }
    __syncthreads();

    // ---- fill input tile transposed: s_in[kk*PITCH + e] ----
    for (int kk = j; kk < KV_IN; kk += 128) {
        float* row = s_in + kk * PITCH;
        if (kk < DN) {
            #pragma unroll 4
            for (int e = 0; e < TE; e++)
                row[e] = h[(size_t)(NDST + e0 + e) * DN + kk];
        } else if (kk < DN + DE) {
            int c = kk - DN;
            #pragma unroll 4
            for (int e = 0; e < TE; e++)
                row[e] = ef[(size_t)(e0 + e) * DE + c];
        } else {
            int c = kk - DN - DE;
            float tw = time_w[c], tb = time_b[c];
            #pragma unroll 4
            for (int e = 0; e < TE; e++)
                row[e] = cosf(fmaf(s_dt[e], tw, tb));
        }
    }
    __syncthreads();

    // ---- register-tiled V GEMM ----
    int wpid = j >> 5, lane = j & 31;
    int eg   = lane >> 3;            // edge group: edges eg*8 .. eg*8+7
    int cg   = lane & 7;             // col group within warp
    int col  = wpid * 32 + cg * 4;   // 4 contiguous output cols

    unsigned long long acc[4][4];    // [edge-pair][col]
    {
        float4 b4 = *(const float4*)(bv + col);
        #pragma unroll
        for (int p = 0; p < 4; p++) {
            acc[p][0] = pack2(b4.x, b4.x);
            acc[p][1] = pack2(b4.y, b4.y);
            acc[p][2] = pack2(b4.z, b4.z);
            acc[p][3] = pack2(b4.w, b4.w);
        }
    }

    const float* wvp = wv + col;
    const float* xbase = s_in + eg * 8;
    #pragma unroll 2
    for (int k = 0; k < KV_IN; k++) {
        float4 w4 = *(const float4*)(wvp + (size_t)k * DOUT);
        unsigned long long wd0 = pack2(w4.x, w4.x);
        unsigned long long wd1 = pack2(w4.y, w4.y);
        unsigned long long wd2 = pack2(w4.z, w4.z);
        unsigned long long wd3 = pack2(w4.w, w4.w);
        const ulonglong2* xr = (const ulonglong2*)(xbase + k * PITCH);
        ulonglong2 xa = xr[0];           // edges eg*8+0..3 (2 pairs)
        ulonglong2 xb = xr[1];           // edges eg*8+4..7 (2 pairs)
        ffma2(acc[0][0], xa.x, wd0); ffma2(acc[0][1], xa.x, wd1);
        ffma2(acc[0][2], xa.x, wd2); ffma2(acc[0][3], xa.x, wd3);
        ffma2(acc[1][0], xa.y, wd0); ffma2(acc[1][1], xa.y, wd1);
        ffma2(acc[1][2], xa.y, wd2); ffma2(acc[1][3], xa.y, wd3);
        ffma2(acc[2][0], xb.x, wd0); ffma2(acc[2][1], xb.x, wd1);
        ffma2(acc[2][2], xb.x, wd2); ffma2(acc[2][3], xb.x, wd3);
        ffma2(acc[3][0], xb.y, wd0); ffma2(acc[3][1], xb.y, wd1);
        ffma2(acc[3][2], xb.y, wd2); ffma2(acc[3][3], xb.y, wd3);
    }

    // ---- scores via QW gather: thread = (edge, head, k-half) ----
    {
        int e    = j >> 2;          // 0..31
        int sub  = j & 3;
        int hh   = sub & 1;
        int half = sub >> 1;
        const float* qwr = g_qw + (size_t)s_dst[e] * QWROW + hh;
        int k0 = half * (KV_IN / 2);          // 0 or 186
        float accs = 0.f;
        #pragma unroll 2
        for (int k = k0; k < k0 + KV_IN / 2; k++)
            accs = fmaf(s_in[k * PITCH + e], qwr[k * HEADS], accs);
        accs += __shfl_down_sync(0xffffffffu, accs, 2);
        if (sub < 2) {
            float sc = accs + s_ab[hh];
            sc = sc > 0.f ? sc : 0.2f * sc;
            float w = expf(sc);
            s_w[e][hh] = w;
            atomicAdd(&g_z[s_dst[e] * HEADS + hh], w);
        }
    }
    __syncthreads();

    // ---- weighted V aggregation straight from registers ----
    int hh = (col >= 64) ? 1 : 0;
    #pragma unroll
    for (int p = 0; p < 4; p++) {
        int ea = eg * 8 + 2 * p, eb = ea + 1;
        float wa = s_w[ea][hh], wb = s_w[eb][hh];
        float* ra = g_agg + (size_t)s_dst[ea] * DOUT + col;
        float* rb = g_agg + (size_t)s_dst[eb] * DOUT + col;
        #pragma unroll
        for (int c = 0; c < 4; c++) {
            float v0, v1; unpack2(acc[p][c], v0, v1);
            atomicAdd(ra + c, v0 * wa);
            atomicAdd(rb + c, v1 * wb);
        }
    }
}

// ---------------- output GEMM + ReLU + LayerNorm ---------------------------
__global__ __launch_bounds__(128) void k_out(
    const float* __restrict__ h,   const float* __restrict__ wout,
    const float* __restrict__ bout, const float* __restrict__ ln_g,
    const float* __restrict__ ln_b, float* __restrict__ out)
{
    int j  = threadIdx.x;
    int n0 = blockIdx.x * 4;
    __shared__ float s_row[4][OUT_IN];
    __shared__ float s_sum[4][4], s_sq[4][4];

    for (int n = 0; n < 4; n++) {
        int d = n0 + n;
        float z0 = g_z[d * HEADS + 0], z1 = g_z[d * HEADS + 1];
        float i0 = z0 > 0.f ? 1.f / z0 : 0.f;
        float i1 = z1 > 0.f ? 1.f / z1 : 0.f;
        for (int k = j; k < DOUT; k += 128)
            s_row[n][k] = g_agg[d * DOUT + k] * (k < 64 ? i0 : i1);
        for (int k = j; k < DN; k += 128)
            s_row[n][DOUT + k] = h[(size_t)d * DN + k];
    }
    __syncthreads();

    float acc[4];
    float bj = bout[j];
    #pragma unroll
    for (int n = 0; n < 4; n++) acc[n] = bj;
    for (int i = 0; i < OUT_IN; i++) {
        float w = wout[i * DOUT + j];
        #pragma unroll
        for (int n = 0; n < 4; n++) acc[n] = fmaf(s_row[n][i], w, acc[n]);
    }
    #pragma unroll
    for (int n = 0; n < 4; n++) acc[n] = acc[n] > 0.f ? acc[n] : 0.f;

    int lane = j & 31, wp = j >> 5;
    #pragma unroll
    for (int n = 0; n < 4; n++) {
        float s = acc[n], q = acc[n] * acc[n];
        #pragma unroll
        for (int o = 16; o; o >>= 1) {
            s += __shfl_down_sync(0xffffffffu, s, o);
            q += __shfl_down_sync(0xffffffffu, q, o);
        }
        if (lane == 0) { s_sum[n][wp] = s; s_sq[n][wp] = q; }
    }
    __syncthreads();

    float gj = ln_g[j], lbj = ln_b[j];
    #pragma unroll
    for (int n = 0; n < 4; n++) {
        float s = s_sum[n][0] + s_sum[n][1] + s_sum[n][2] + s_sum[n][3];
        float q = s_sq[n][0]  + s_sq[n][1]  + s_sq[n][2]  + s_sq[n][3];
        float mean = s * (1.f / DOUT);
        float var  = q * (1.f / DOUT) - mean * mean;
        float r    = rsqrtf(var + 1e-5f);
        out[(size_t)(n0 + n) * DOUT + j] = (acc[n] - mean) * r * gj + lbj;
    }
}

// ---------------- launch ----------------------------------------------------
extern "C" void kernel_launch(void* const* d_in, const int* in_sizes, int n_in,
                              void* d_out, int out_size)
{
    const float* h        = (const float*)d_in[0];
    const float* ef       = (const float*)d_in[1];
    const float* dt       = (const float*)d_in[2];
    const int*   dst_idx  = (const int*)  d_in[3];
    const float* time_w   = (const float*)d_in[5];
    const float* time_b   = (const float*)d_in[6];
    const float* wq       = (const float*)d_in[7];
    const float* bq       = (const float*)d_in[8];
    const float* wk       = (const float*)d_in[9];
    const float* wv       = (const float*)d_in[11];
    const float* bv       = (const float*)d_in[12];
    const float* att_bias = (const float*)d_in[13];
    const float* wout     = (const float*)d_in[14];
    const float* bout     = (const float*)d_in[15];
    const float* ln_g     = (const float*)d_in[16];
    const float* ln_b     = (const float*)d_in[17];
    float* out = (float*)d_out;

    static int smem_set = 0;
    if (!smem_set) {
        cudaFuncSetAttribute(k_edge, cudaFuncAttributeMaxDynamicSharedMemorySize,
                             SMEM_EDGE_BYTES);
        smem_set = 1;
    }

    k_init<<<512, 256>>>();
    k_qnodes<<<NDST / 4, 128>>>(h, wq, bq, time_b);
    k_qw<<<NDST / QWN, 128>>>(wk);
    k_edge<<<E_TOTAL / TE, 128, SMEM_EDGE_BYTES>>>(
        h, ef, dt, dst_idx, time_w, time_b, wv, bv, att_bias);
    k_out<<<NDST / 4, 128>>>(h, wout, bout, ln_g, ln_b, out);
}

// round 12
// speedup vs baseline: 1.2216x; 1.2216x over previous
#include <cuda_runtime.h>
#include <cuda_bf16.h>
#include <math.h>
#include <stdint.h>

// ---------------- problem constants ----------------------------------------
#define E_TOTAL 600000
#define NDST    10000
#define DN      100
#define DE      172
#define DTF     100
#define DOUT    128
#define HEADS   2
#define KV_IN   372   // DN + DE + DTF
#define KPAD    384
#define OUT_IN  228   // DOUT + DN
#define QWROW   (KV_IN * HEADS)   // 744
#define QWN     8
#define MT      64    // edges per block in k_edge
#define NBLK    (E_TOTAL / MT)    // 9375
#define CHK     192   // k per chunk
#define PKA     200   // A smem pitch (bf16 elems): 400B rows -> bank-shift 4
#define SMEM_EDGE_BYTES (MT * PKA * 2 * 2)   // hi+lo planes = 51200 B

// ---------------- scratch (device globals) ---------------------------------
__device__ float g_qnodes[NDST * DOUT];
__device__ float g_qw[NDST * QWROW];  // QW[d][k][h]
__device__ float g_qb[NDST * HEADS];  // fold of bk into Q
__device__ float g_z[NDST * HEADS];
__device__ float g_agg[NDST * DOUT];
// wv transposed [n][k] split-bf16 (k padded to 384)
__device__ __nv_bfloat16 g_BT_hi[DOUT * KPAD];
__device__ __nv_bfloat16 g_BT_lo[DOUT * KPAD];

// ---------------- mma.sync helper ------------------------------------------
__device__ __forceinline__ void mma16816(float* c, const uint32_t* a,
                                         const uint32_t* b) {
    asm volatile(
        "mma.sync.aligned.m16n8k16.row.col.f32.bf16.bf16.f32 "
        "{%0,%1,%2,%3}, {%4,%5,%6,%7}, {%8,%9}, {%0,%1,%2,%3};"
        : "+f"(c[0]), "+f"(c[1]), "+f"(c[2]), "+f"(c[3])
        : "r"(a[0]), "r"(a[1]), "r"(a[2]), "r"(a[3]), "r"(b[0]), "r"(b[1]));
}

// ---------------- init ------------------------------------------------------
__global__ void k_init() {
    int i = blockIdx.x * blockDim.x + threadIdx.x;
    int stride = gridDim.x * blockDim.x;
    for (int k = i; k < NDST * HEADS; k += stride) g_z[k] = 0.f;
    for (int k = i; k < NDST * DOUT; k += stride)  g_agg[k] = 0.f;
}

// ---------------- prep B: wv -> transposed split-bf16 ----------------------
__global__ void k_prepB(const float* __restrict__ wv) {
    int i = blockIdx.x * blockDim.x + threadIdx.x;
    if (i >= DOUT * KPAD) return;
    int n = i / KPAD, k = i % KPAD;
    float v = (k < KV_IN) ? wv[k * DOUT + n] : 0.f;
    __nv_bfloat16 hi = __float2bfloat16(v);
    g_BT_hi[i] = hi;
    g_BT_lo[i] = __float2bfloat16(v - __bfloat162float(hi));
}

// ---------------- Q per dst node -------------------------------------------
__global__ __launch_bounds__(128) void k_qnodes(
    const float* __restrict__ h, const float* __restrict__ wq,
    const float* __restrict__ bq, const float* __restrict__ time_b)
{
    int j  = threadIdx.x;
    int n0 = blockIdx.x * 4;
    __shared__ float sh[4][DN];
    for (int idx = j; idx < 4 * DN; idx += 128) {
        int n = idx / DN, i = idx % DN;
        sh[n][i] = h[(size_t)(n0 + n) * DN + i];
    }
    __syncthreads();
    float qc = bq[j];
    for (int i = 0; i < DTF; i++)
        qc = fmaf(wq[(DN + i) * DOUT + j], cosf(time_b[i]), qc);
    float a0 = qc, a1 = qc, a2 = qc, a3 = qc;
    for (int i = 0; i < DN; i++) {
        float w = wq[i * DOUT + j];
        a0 = fmaf(sh[0][i], w, a0);
        a1 = fmaf(sh[1][i], w, a1);
        a2 = fmaf(sh[2][i], w, a2);
        a3 = fmaf(sh[3][i], w, a3);
    }
    g_qnodes[(n0 + 0) * DOUT + j] = a0;
    g_qnodes[(n0 + 1) * DOUT + j] = a1;
    g_qnodes[(n0 + 2) * DOUT + j] = a2;
    g_qnodes[(n0 + 3) * DOUT + j] = a3;
}

// ---------------- QW table: fold Q into wk ---------------------------------
__global__ __launch_bounds__(128) void k_qw(const float* __restrict__ wk) {
    int n0 = blockIdx.x * QWN;
    __shared__ float sq[QWN][DOUT];
    for (int idx = threadIdx.x; idx < QWN * DOUT; idx += 128) {
        int n = idx >> 7, j = idx & 127;
        sq[n][j] = g_qnodes[(size_t)(n0 + n) * DOUT + j];
    }
    __syncthreads();
    for (int k = threadIdx.x; k < KV_IN; k += 128) {
        const float* wr = wk + (size_t)k * DOUT;
        #pragma unroll
        for (int hh = 0; hh < HEADS; hh++) {
            float a[QWN];
            #pragma unroll
            for (int n = 0; n < QWN; n++) a[n] = 0.f;
            for (int j = 0; j < 64; j++) {
                float w = wr[hh * 64 + j];
                #pragma unroll
                for (int n = 0; n < QWN; n++)
                    a[n] = fmaf(sq[n][hh * 64 + j], w, a[n]);
            }
            #pragma unroll
            for (int n = 0; n < QWN; n++)
                g_qw[(size_t)(n0 + n) * QWROW + k * HEADS + hh] = a[n];
        }
    }
}

// ---------------- fold bk into per-(dst,head) score constant ---------------
__global__ void k_qb(const float* __restrict__ bk) {
    int i = blockIdx.x * blockDim.x + threadIdx.x;
    if (i >= NDST * HEADS) return;
    int d = i >> 1, hh = i & 1;
    float s = 0.f;
    for (int j = 0; j < 64; j++)
        s = fmaf(g_qnodes[(size_t)d * DOUT + hh * 64 + j], bk[hh * 64 + j], s);
    g_qb[i] = s;
}

// ---------------- HMMA edge kernel -----------------------------------------
// V[64x128] = X[64x384] * wv via split-bf16 mma.sync (3 terms).
// Scores computed in fp32 during the fill (QW trick), exp w/o max-sub,
// z/agg via L2 atomics.
__global__ __launch_bounds__(256, 2) void k_edge(
    const float* __restrict__ h,  const float* __restrict__ ef,
    const float* __restrict__ dt, const int*   __restrict__ dst_idx,
    const float* __restrict__ time_w, const float* __restrict__ time_b,
    const float* __restrict__ bv, const float* __restrict__ att_bias)
{
    extern __shared__ unsigned char dsm[];
    __nv_bfloat16* sAhi = (__nv_bfloat16*)dsm;               // [MT][PKA]
    __nv_bfloat16* sAlo = sAhi + MT * PKA;
    __shared__ int   s_dst[MT];
    __shared__ float s_dtv[MT];
    __shared__ float s_w[MT][HEADS];
    __shared__ float s_ab[2];

    int t   = threadIdx.x;
    int e0  = blockIdx.x * MT;
    int wid = t >> 5, lane = t & 31;
    int g   = lane >> 2, tq = lane & 3;
    int n0  = wid * 16;

    if (t < MT) { s_dst[t] = dst_idx[e0 + t]; s_dtv[t] = dt[e0 + t]; }
    if (t < 2) {
        float s = 0.f;
        #pragma unroll 8
        for (int i = 0; i < 64; i++) s += att_bias[t * 64 + i];
        s_ab[t] = s;
    }
    __syncthreads();

    int   e   = t >> 2, sub = t & 3;
    int   ge  = e0 + e;
    int   d_e = s_dst[e];
    float tte = s_dtv[e];
    const float* qwr = g_qw + (size_t)d_e * QWROW;

    float Dv[4][2][4];
    #pragma unroll
    for (int i = 0; i < 4; i++)
        #pragma unroll
        for (int jn = 0; jn < 2; jn++)
            #pragma unroll
            for (int c = 0; c < 4; c++) Dv[i][jn][c] = 0.f;

    float sc0 = 0.f, sc1 = 0.f;

    for (int c = 0; c < 2; c++) {
        if (c > 0) __syncthreads();   // prior chunk's mma reads done

        // ---- fill A chunk: fp32 x -> score partials + split-bf16 smem ----
        int kb = sub * 48;
        for (int i = 0; i < 48; i++) {
            int kk = kb + i;
            int k  = c * CHK + kk;
            float v = 0.f;
            if (k < DN)            v = h[(size_t)(NDST + ge) * DN + k];
            else if (k < DN + DE)  v = ef[(size_t)ge * DE + (k - DN)];
            else if (k < KV_IN)    v = cosf(fmaf(tte, time_w[k - DN - DE],
                                                 time_b[k - DN - DE]));
            if (k < KV_IN) {
                float2 q2 = *(const float2*)(qwr + k * 2);
                sc0 = fmaf(v, q2.x, sc0);
                sc1 = fmaf(v, q2.y, sc1);
            }
            __nv_bfloat16 hi = __float2bfloat16(v);
            sAhi[e * PKA + kk] = hi;
            sAlo[e * PKA + kk] = __float2bfloat16(v - __bfloat162float(hi));
        }
        __syncthreads();

        // ---- 12 k-steps of m16n8k16 ----
        for (int s = 0; s < 12; s++) {
            int kk = s * 16;
            int gk = c * CHK + kk;
            uint32_t bh[2][2], bl[2][2];
            #pragma unroll
            for (int jn = 0; jn < 2; jn++) {
                int n = n0 + jn * 8 + g;
                const __nv_bfloat16* ph = g_BT_hi + (size_t)n * KPAD + gk + 2 * tq;
                const __nv_bfloat16* pl = g_BT_lo + (size_t)n * KPAD + gk + 2 * tq;
                bh[jn][0] = *(const uint32_t*)(ph);
                bh[jn][1] = *(const uint32_t*)(ph + 8);
                bl[jn][0] = *(const uint32_t*)(pl);
                bl[jn][1] = *(const uint32_t*)(pl + 8);
            }
            #pragma unroll
            for (int i = 0; i < 4; i++) {
                int r0 = i * 16 + g, r1 = r0 + 8;
                uint32_t ah[4], al[4];
                ah[0] = *(const uint32_t*)(sAhi + r0 * PKA + kk + 2 * tq);
                ah[1] = *(const uint32_t*)(sAhi + r1 * PKA + kk + 2 * tq);
                ah[2] = *(const uint32_t*)(sAhi + r0 * PKA + kk + 8 + 2 * tq);
                ah[3] = *(const uint32_t*)(sAhi + r1 * PKA + kk + 8 + 2 * tq);
                al[0] = *(const uint32_t*)(sAlo + r0 * PKA + kk + 2 * tq);
                al[1] = *(const uint32_t*)(sAlo + r1 * PKA + kk + 2 * tq);
                al[2] = *(const uint32_t*)(sAlo + r0 * PKA + kk + 8 + 2 * tq);
                al[3] = *(const uint32_t*)(sAlo + r1 * PKA + kk + 8 + 2 * tq);
                #pragma unroll
                for (int jn = 0; jn < 2; jn++) {
                    mma16816(Dv[i][jn], ah, bh[jn]);
                    mma16816(Dv[i][jn], al, bh[jn]);
                    mma16816(Dv[i][jn], ah, bl[jn]);
                }
            }
        }
    }

    // ---- scores: reduce 4-lane partials, leaky, exp, z ----
    sc0 += __shfl_down_sync(0xffffffffu, sc0, 2, 4);
    sc0 += __shfl_down_sync(0xffffffffu, sc0, 1, 4);
    sc1 += __shfl_down_sync(0xffffffffu, sc1, 2, 4);
    sc1 += __shfl_down_sync(0xffffffffu, sc1, 1, 4);
    if (sub == 0) {
        float a0 = sc0 + s_ab[0] + g_qb[d_e * HEADS + 0];
        float a1 = sc1 + s_ab[1] + g_qb[d_e * HEADS + 1];
        a0 = a0 > 0.f ? a0 : 0.2f * a0;
        a1 = a1 > 0.f ? a1 : 0.2f * a1;
        float w0 = expf(a0), w1 = expf(a1);
        s_w[e][0] = w0; s_w[e][1] = w1;
        atomicAdd(&g_z[d_e * HEADS + 0], w0);
        atomicAdd(&g_z[d_e * HEADS + 1], w1);
    }
    __syncthreads();

    // ---- weighted aggregation from fragments ----
    int hh = wid >> 2;   // cols [0,64) head 0, [64,128) head 1
    #pragma unroll
    for (int jn = 0; jn < 2; jn++) {
        int n = n0 + jn * 8 + 2 * tq;
        float bv0 = bv[n], bv1 = bv[n + 1];
        #pragma unroll
        for (int i = 0; i < 4; i++) {
            int ea = i * 16 + g, eb = ea + 8;
            float wa = s_w[ea][hh], wb = s_w[eb][hh];
            float* pa = g_agg + (size_t)s_dst[ea] * DOUT + n;
            float* pb = g_agg + (size_t)s_dst[eb] * DOUT + n;
            atomicAdd(pa,     (Dv[i][jn][0] + bv0) * wa);
            atomicAdd(pa + 1, (Dv[i][jn][1] + bv1) * wa);
            atomicAdd(pb,     (Dv[i][jn][2] + bv0) * wb);
            atomicAdd(pb + 1, (Dv[i][jn][3] + bv1) * wb);
        }
    }
}

// ---------------- output GEMM + ReLU + LayerNorm ---------------------------
__global__ __launch_bounds__(128) void k_out(
    const float* __restrict__ h,   const float* __restrict__ wout,
    const float* __restrict__ bout, const float* __restrict__ ln_g,
    const float* __restrict__ ln_b, float* __restrict__ out)
{
    int j  = threadIdx.x;
    int n0 = blockIdx.x * 4;
    __shared__ float s_row[4][OUT_IN];
    __shared__ float s_sum[4][4], s_sq[4][4];

    for (int n = 0; n < 4; n++) {
        int d = n0 + n;
        float z0 = g_z[d * HEADS + 0], z1 = g_z[d * HEADS + 1];
        float i0 = z0 > 0.f ? 1.f / z0 : 0.f;
        float i1 = z1 > 0.f ? 1.f / z1 : 0.f;
        for (int k = j; k < DOUT; k += 128)
            s_row[n][k] = g_agg[d * DOUT + k] * (k < 64 ? i0 : i1);
        for (int k = j; k < DN; k += 128)
            s_row[n][DOUT + k] = h[(size_t)d * DN + k];
    }
    __syncthreads();

    float acc[4];
    float bj = bout[j];
    #pragma unroll
    for (int n = 0; n < 4; n++) acc[n] = bj;
    for (int i = 0; i < OUT_IN; i++) {
        float w = wout[i * DOUT + j];
        #pragma unroll
        for (int n = 0; n < 4; n++) acc[n] = fmaf(s_row[n][i], w, acc[n]);
    }
    #pragma unroll
    for (int n = 0; n < 4; n++) acc[n] = acc[n] > 0.f ? acc[n] : 0.f;

    int lane = j & 31, wp = j >> 5;
    #pragma unroll
    for (int n = 0; n < 4; n++) {
        float s = acc[n], q = acc[n] * acc[n];
        #pragma unroll
        for (int o = 16; o; o >>= 1) {
            s += __shfl_down_sync(0xffffffffu, s, o);
            q += __shfl_down_sync(0xffffffffu, q, o);
        }
        if (lane == 0) { s_sum[n][wp] = s; s_sq[n][wp] = q; }
    }
    __syncthreads();

    float gj = ln_g[j], lbj = ln_b[j];
    #pragma unroll
    for (int n = 0; n < 4; n++) {
        float s = s_sum[n][0] + s_sum[n][1] + s_sum[n][2] + s_sum[n][3];
        float q = s_sq[n][0]  + s_sq[n][1]  + s_sq[n][2]  + s_sq[n][3];
        float mean = s * (1.f / DOUT);
        float var  = q * (1.f / DOUT) - mean * mean;
        float r    = rsqrtf(var + 1e-5f);
        out[(size_t)(n0 + n) * DOUT + j] = (acc[n] - mean) * r * gj + lbj;
    }
}

// ---------------- launch ----------------------------------------------------
extern "C" void kernel_launch(void* const* d_in, const int* in_sizes, int n_in,
                              void* d_out, int out_size)
{
    const float* h        = (const float*)d_in[0];
    const float* ef       = (const float*)d_in[1];
    const float* dt       = (const float*)d_in[2];
    const int*   dst_idx  = (const int*)  d_in[3];
    const float* time_w   = (const float*)d_in[5];
    const float* time_b   = (const float*)d_in[6];
    const float* wq       = (const float*)d_in[7];
    const float* bq       = (const float*)d_in[8];
    const float* wk       = (const float*)d_in[9];
    const float* bk       = (const float*)d_in[10];
    const float* wv       = (const float*)d_in[11];
    const float* bv       = (const float*)d_in[12];
    const float* att_bias = (const float*)d_in[13];
    const float* wout     = (const float*)d_in[14];
    const float* bout     = (const float*)d_in[15];
    const float* ln_g     = (const float*)d_in[16];
    const float* ln_b     = (const float*)d_in[17];
    float* out = (float*)d_out;

    static int smem_set = 0;
    if (!smem_set) {
        cudaFuncSetAttribute(k_edge, cudaFuncAttributeMaxDynamicSharedMemorySize,
                             SMEM_EDGE_BYTES);
        smem_set = 1;
    }

    k_init<<<512, 256>>>();
    k_prepB<<<(DOUT * KPAD + 255) / 256, 256>>>(wv);
    k_qnodes<<<NDST / 4, 128>>>(h, wq, bq, time_b);
    k_qw<<<NDST / QWN, 128>>>(wk);
    k_qb<<<(NDST * HEADS + 255) / 256, 256>>>(bk);
    k_edge<<<NBLK, 256, SMEM_EDGE_BYTES>>>(
        h, ef, dt, dst_idx, time_w, time_b, bv, att_bias);
    k_out<<<NDST / 4, 128>>>(h, wout, bout, ln_g, ln_b, out);
}